// round 13
// baseline (speedup 1.0000x reference)
#include <cuda_runtime.h>
#include <cuda_bf16.h>
#include <cstdint>

#define HH 1024
#define BB 64
#define LLEN 1024
#define VV 50257

// ---------------- split-bf16 helpers ----------------
__device__ __forceinline__ uint32_t pack_bf16x2(float lo, float hi) {
    uint32_t r;
    asm("cvt.rn.satfinite.bf16x2.f32 %0, %1, %2;" : "=r"(r) : "f"(hi), "f"(lo));
    return r;
}

__device__ __forceinline__ void split2(float2 v, uint32_t& hi, uint32_t& lo) {
    hi = pack_bf16x2(v.x, v.y);
    float lx = v.x - __uint_as_float(hi << 16);
    float ly = v.y - __uint_as_float(hi & 0xFFFF0000u);
    lo = pack_bf16x2(lx, ly);
}

__device__ __forceinline__ void mma16816(float* c,
                                         uint32_t a0, uint32_t a1, uint32_t a2, uint32_t a3,
                                         uint32_t b0, uint32_t b1) {
    asm volatile(
        "mma.sync.aligned.m16n8k16.row.col.f32.bf16.bf16.f32 "
        "{%0,%1,%2,%3}, {%4,%5,%6,%7}, {%8,%9}, {%0,%1,%2,%3};"
        : "+f"(c[0]), "+f"(c[1]), "+f"(c[2]), "+f"(c[3])
        : "r"(a0), "r"(a1), "r"(a2), "r"(a3), "r"(b0), "r"(b1));
}

// ---------------- cp.async helpers ----------------
__device__ __forceinline__ void cp_async16(uint32_t dst, const void* src, int szbytes) {
    asm volatile("cp.async.cg.shared.global [%0], [%1], 16, %2;"
                 :: "r"(dst), "l"(src), "r"(szbytes) : "memory");
}
__device__ __forceinline__ void cp_commit() {
    asm volatile("cp.async.commit_group;" ::: "memory");
}
__device__ __forceinline__ void cp_wait1() {
    asm volatile("cp.async.wait_group 1;" ::: "memory");
}
__device__ __forceinline__ void cp_wait2() {
    asm volatile("cp.async.wait_group 2;" ::: "memory");
}

// ---------------- scratch layout (floats) ----------------
// XP 0 | HP0 65536 | HP1 131072 | GX 196608(4x196608) | GH 983040(4x196608)
// E 1769472(65536) | MS 1835008(1024) | PCTX 1836032(524288)
// RNN 2360320(65536) | CINP 2425856(131072) | CC 2556928(16x65536)
// COUTP 3605504(65536) | LOG 3671040(2x3216448)  total 10103936
__device__ float g_scratch[10103936];

// ============ pack inputs: emb[idx] -> XP, last_h[0] -> HP0, last_h[1] -> HP1 ============
__global__ void __launch_bounds__(256) k_pack3(
    const float* __restrict__ emb, const int* __restrict__ idx,
    const float* __restrict__ h0, const float* __restrict__ h1,
    float* __restrict__ XP, float* __restrict__ HP0, float* __restrict__ HP1)
{
    int i = blockIdx.x * 256 + threadIdx.x;
    int lane = i & 31, nf = (i >> 5) & 7, t = i >> 8;
    int g = lane >> 2, tig = lane & 3;
    int n = nf * 8 + g;
    int k0 = t * 16 + tig * 2;
    const float* src;
    float* dst;
    if (blockIdx.y == 0)      { src = emb + (size_t)idx[n] * HH; dst = XP; }
    else if (blockIdx.y == 1) { src = h0 + (size_t)n * HH;       dst = HP0; }
    else                      { src = h1 + (size_t)n * HH;       dst = HP1; }
    float2 v0 = __ldg((const float2*)(src + k0));
    float2 v1 = __ldg((const float2*)(src + k0 + 8));
    uint32_t h0b, l0b, h1b, l1b;
    split2(v0, h0b, l0b);
    split2(v1, h1b, l1b);
    ((uint4*)dst)[i] = make_uint4(h0b, h1b, l0b, l1b);
}

// ============ sum 16 concat K-slices + bias + tanh, split-pack for W_out ============
__global__ void __launch_bounds__(256) k_pack_cout(
    const float* __restrict__ cc, const float* __restrict__ bias,
    float* __restrict__ dst)
{
    int i = blockIdx.x * 256 + threadIdx.x;
    int lane = i & 31, nf = (i >> 5) & 7, t = i >> 8;
    int g = lane >> 2, tig = lane & 3;
    int n = nf * 8 + g;
    int k0 = t * 16 + tig * 2;
    size_t base = (size_t)n * HH;
    float e0 = bias[k0], e1 = bias[k0 + 1], e2 = bias[k0 + 8], e3 = bias[k0 + 9];
#pragma unroll
    for (int z = 0; z < 16; ++z) {
        const float* p = cc + (size_t)z * 65536 + base;
        e0 += p[k0]; e1 += p[k0 + 1]; e2 += p[k0 + 8]; e3 += p[k0 + 9];
    }
    e0 = tanhf(e0); e1 = tanhf(e1); e2 = tanhf(e2); e3 = tanhf(e3);
    uint32_t h0, l0, h1, l1;
    split2(make_float2(e0, e1), h0, l0);
    split2(make_float2(e2, e3), h1, l1);
    ((uint4*)dst)[i] = make_uint4(h0, h1, l0, l1);
}

// ============ split-bf16 HMMA GEMM: cp.async ring + cooperative W pre-split ============
// 256 thr = 8 warps x 16 rows (128-row M tile). Stage layout:
//   [0,10240)      raw W fp32, 128 rows x 16 k @ 80B row stride (cp.async dest)
//   [10240,14336)  packed B (uint4 per lane x 256)
//   [14336,24576)  split W: per row 20 uint32 (hi c2 0..7, lo 8..15, pad) -- bank-clean
// Pipeline per kstep: wait raw[t+1]; barrier; issue raw[t+3]; convert raw[t+1]->split[t+1];
// consume split[t] (8 LDS.32 + 8 LDS.128 + 24 MMA, zero conversion in consumer path).
#define STAGE_BYTES 24576
#define GEMM_SMEM   (4 * STAGE_BYTES)

__global__ void __launch_bounds__(256) k_gemm(
    const float* __restrict__ W, const uint4* __restrict__ P,
    float* __restrict__ out, int Nout, int K, int tps,
    const float* W2, const uint4* P2, float* out2)
{
    if (blockIdx.y == 1) { W = W2; P = P2; out = out2; }

    extern __shared__ char smem[];
    const uint32_t sbase = (uint32_t)__cvta_generic_to_shared(smem);

    const int tid = threadIdx.x;
    const int wid = tid >> 5;
    const int lane = tid & 31;
    const int g = lane >> 2;
    const int tig = lane & 3;

    const int m0 = blockIdx.x * 128;
    const int mA0 = m0 + wid * 16 + g, mA1 = mA0 + 8;
    const bool vA0 = mA0 < Nout, vA1 = mA1 < Nout;

    const int t0 = blockIdx.z * tps;
    const uint4* Pt = P + (size_t)t0 * 256;

    // cp.async sources/dests (two W rows + one B chunk per thread)
    const int rowc0 = tid >> 2, colq = tid & 3;
    const int rowc1 = rowc0 + 64;
    const int mgc0 = m0 + rowc0, mgc1 = m0 + rowc1;
    const float* Wc0 = W + (size_t)(mgc0 < Nout ? mgc0 : 0) * K + colq * 4 + t0 * 16;
    const float* Wc1 = W + (size_t)(mgc1 < Nout ? mgc1 : 0) * K + colq * 4 + t0 * 16;
    const int sz0 = mgc0 < Nout ? 16 : 0;   // 0 -> cp.async zero-fill
    const int sz1 = mgc1 < Nout ? 16 : 0;
    const uint32_t dW0 = sbase + rowc0 * 80 + colq * 16;
    const uint32_t dW1 = sbase + rowc1 * 80 + colq * 16;
    const uint32_t dB  = sbase + 10240 + tid * 16;

    // convert-pass mapping: thread -> (row, half)
    const int cr = tid >> 1, chalf = tid & 1;

    float acc[8][4];
#pragma unroll
    for (int nf = 0; nf < 8; ++nf)
#pragma unroll
        for (int j = 0; j < 4; ++j) acc[nf][j] = 0.f;

#define ISSUE_K(t, sl) do { \
    const uint32_t _so = (uint32_t)(sl) * STAGE_BYTES; \
    cp_async16(dW0 + _so, Wc0 + (size_t)(t) * 16, sz0); \
    cp_async16(dW1 + _so, Wc1 + (size_t)(t) * 16, sz1); \
    cp_async16(dB + _so, Pt + (size_t)(t) * 256 + tid, 16); \
} while (0)

// cooperative convert: raw fp32 -> split hi/lo fragments
#define CONVERT_K(sl) do { \
    const char* _raw = smem + (sl) * STAGE_BYTES; \
    uint32_t* _sp = (uint32_t*)(smem + (sl) * STAGE_BYTES + 14336); \
    const float2* _src = (const float2*)(_raw + cr * 80 + chalf * 32); \
    uint32_t _hi[4], _lo[4]; \
    _Pragma("unroll") \
    for (int _j = 0; _j < 4; ++_j) split2(_src[_j], _hi[_j], _lo[_j]); \
    uint32_t* _dst = _sp + cr * 20 + chalf * 4; \
    *(uint2*)(_dst)      = make_uint2(_hi[0], _hi[1]); \
    *(uint2*)(_dst + 2)  = make_uint2(_hi[2], _hi[3]); \
    *(uint2*)(_dst + 8)  = make_uint2(_lo[0], _lo[1]); \
    *(uint2*)(_dst + 10) = make_uint2(_lo[2], _lo[3]); \
} while (0)

// consume: pure LDS + MMA
#define CONSUME_K(sl) do { \
    const uint32_t* _sp = (const uint32_t*)(smem + (sl) * STAGE_BYTES + 14336); \
    const uint4* _sB = (const uint4*)(smem + (sl) * STAGE_BYTES + 10240); \
    const int _r0 = wid * 16 + g; \
    const uint32_t* _p0 = _sp + _r0 * 20; \
    const uint32_t* _p1 = _sp + (_r0 + 8) * 20; \
    uint32_t ah0 = _p0[tig],     ah2 = _p0[tig + 4]; \
    uint32_t al0 = _p0[tig + 8], al2 = _p0[tig + 12]; \
    uint32_t ah1 = _p1[tig],     ah3 = _p1[tig + 4]; \
    uint32_t al1 = _p1[tig + 8], al3 = _p1[tig + 12]; \
    _Pragma("unroll") \
    for (int nf = 0; nf < 8; ++nf) { \
        uint4 b = _sB[nf * 32 + lane]; \
        mma16816(acc[nf], ah0, ah1, ah2, ah3, b.x, b.y); \
        mma16816(acc[nf], ah0, ah1, ah2, ah3, b.z, b.w); \
        mma16816(acc[nf], al0, al1, al2, al3, b.x, b.y); \
    } \
} while (0)

    // prologue: 3 groups in flight, convert stage 0
    ISSUE_K(0, 0); cp_commit();
    ISSUE_K(1, 1); cp_commit();
    ISSUE_K(2, 2); cp_commit();
    cp_wait2();            // group 0 done
    __syncthreads();
    CONVERT_K(0);

    for (int t = 0; t < tps; ++t) {
        cp_wait1();        // raw[t+1] landed
        __syncthreads();   // raw[t+1] visible; split[t] (prev iter) visible; slots reusable

        if (t + 3 < tps) ISSUE_K(t + 3, (t + 3) & 3);
        cp_commit();       // uniform group count (empty groups ok)

        if (t + 1 < tps) CONVERT_K((t + 1) & 3);
        CONSUME_K(t & 3);
    }

    float* os = out + (size_t)blockIdx.z * 64 * Nout;
#pragma unroll
    for (int nf = 0; nf < 8; ++nf) {
        const int n0 = nf * 8 + tig * 2;
        if (vA0) {
            os[(size_t)n0 * Nout + mA0]       = acc[nf][0];
            os[(size_t)(n0 + 1) * Nout + mA0] = acc[nf][1];
        }
        if (vA1) {
            os[(size_t)n0 * Nout + mA1]       = acc[nf][2];
            os[(size_t)(n0 + 1) * Nout + mA1] = acc[nf][3];
        }
    }
#undef ISSUE_K
#undef CONVERT_K
#undef CONSUME_K
}

// ================= logits reduce: sum 2 K-slices + bias =================
__global__ void __launch_bounds__(256) k_lred(
    const float* __restrict__ L, const float* __restrict__ bias,
    float* __restrict__ out)
{
    int m = blockIdx.x * 256 + threadIdx.x;
    int n = blockIdx.y;
    if (m < VV) {
        size_t i = (size_t)n * VV + m;
        out[i] = __ldg(L + i) + __ldg(L + i + (size_t)64 * VV) + __ldg(bias + m);
    }
}

// ============ GRU gates (4 K-slices), fused with next-stage packing ============
__global__ void __launch_bounds__(128) k_gates(
    const float* __restrict__ gx, const float* __restrict__ gh,
    const float* __restrict__ bih, const float* __restrict__ bhh,
    const float* __restrict__ hprev, float* __restrict__ out_hid,
    float* __restrict__ packed, float* __restrict__ rnn_fp32)
{
    const int b = blockIdx.x;
    const int t = threadIdx.x;
    const int ts = blockIdx.y * 32 + (t >> 2);
    const int tig = t & 3;
    const int j0 = ts * 16 + tig * 2;

    float h[4];
#pragma unroll
    for (int p = 0; p < 2; ++p) {
        const int j = j0 + p * 8;
        float2 gr = __ldg((const float2*)(bih + j));
        float2 gz = __ldg((const float2*)(bih + j + 1024));
        float2 gn = __ldg((const float2*)(bih + j + 2048));
        float2 hr = __ldg((const float2*)(bhh + j));
        float2 hz = __ldg((const float2*)(bhh + j + 1024));
        float2 hn = __ldg((const float2*)(bhh + j + 2048));
        const size_t o = (size_t)b * 3072 + j;
#pragma unroll
        for (int s = 0; s < 4; ++s) {
            const float* px = gx + (size_t)s * 196608 + o;
            const float* ph = gh + (size_t)s * 196608 + o;
            float2 v;
            v = __ldg((const float2*)px);          gr.x += v.x; gr.y += v.y;
            v = __ldg((const float2*)(px + 1024)); gz.x += v.x; gz.y += v.y;
            v = __ldg((const float2*)(px + 2048)); gn.x += v.x; gn.y += v.y;
            v = __ldg((const float2*)ph);          hr.x += v.x; hr.y += v.y;
            v = __ldg((const float2*)(ph + 1024)); hz.x += v.x; hz.y += v.y;
            v = __ldg((const float2*)(ph + 2048)); hn.x += v.x; hn.y += v.y;
        }
        float rx = 1.f / (1.f + __expf(-(gr.x + hr.x)));
        float ry = 1.f / (1.f + __expf(-(gr.y + hr.y)));
        float zx = 1.f / (1.f + __expf(-(gz.x + hz.x)));
        float zy = 1.f / (1.f + __expf(-(gz.y + hz.y)));
        float nx = tanhf(gn.x + rx * hn.x);
        float ny = tanhf(gn.y + ry * hn.y);
        float2 hp = __ldg((const float2*)(hprev + (size_t)b * 1024 + j));
        h[p * 2]     = (1.f - zx) * nx + zx * hp.x;
        h[p * 2 + 1] = (1.f - zy) * ny + zy * hp.y;
        out_hid[(size_t)b * 1024 + j]     = h[p * 2];
        out_hid[(size_t)b * 1024 + j + 1] = h[p * 2 + 1];
        if (rnn_fp32) {
            rnn_fp32[(size_t)b * 1024 + j]     = h[p * 2];
            rnn_fp32[(size_t)b * 1024 + j + 1] = h[p * 2 + 1];
        }
    }

    uint32_t h01h, h01l, h23h, h23l;
    split2(make_float2(h[0], h[1]), h01h, h01l);
    split2(make_float2(h[2], h[3]), h23h, h23l);
    const int nf = b >> 3, lane = (b & 7) * 4 + tig;
    ((uint4*)packed)[(ts * 8 + nf) * 32 + lane] = make_uint4(h01h, h23h, h01l, h23l);
}

// ============ fused attention: energy + online softmax + partial context ============
__global__ void __launch_bounds__(256) k_attn_fused(
    const float* __restrict__ rnn,
    const float* __restrict__ enc,
    float* __restrict__ E, float* __restrict__ MS, float* __restrict__ PCTX)
{
    __shared__ float sx[HH];
    __shared__ float sce[16];
    const int chunk = blockIdx.x, b = blockIdx.y;
    const int tid = threadIdx.x;
    const int wid = tid >> 5, lane = tid & 31;

    const float4* src = (const float4*)(rnn + (size_t)b * HH);
    for (int i = tid; i < HH / 4; i += 256)
        ((float4*)sx)[i] = src[i];
    __syncthreads();

    float M = -1e30f, S = 0.f;
    float4 a = make_float4(0.f, 0.f, 0.f, 0.f);
    const float4* sx4 = (const float4*)sx;

    for (int sub = 0; sub < 8; ++sub) {
        const int lbase = chunk * 128 + sub * 16;
#pragma unroll
        for (int j = 0; j < 2; ++j) {
            const int l = lbase + wid * 2 + j;
            const float4* e4 = (const float4*)(enc + ((size_t)l * BB + b) * HH);
            float acc = 0.f;
#pragma unroll
            for (int i = 0; i < 8; ++i) {
                float4 v = __ldg(e4 + lane + i * 32);
                float4 x = sx4[lane + i * 32];
                acc += v.x * x.x + v.y * x.y + v.z * x.z + v.w * x.w;
            }
#pragma unroll
            for (int o = 16; o; o >>= 1) acc += __shfl_xor_sync(0xffffffffu, acc, o);
            if (lane == 0) {
                sce[wid * 2 + j] = acc;
                E[(size_t)b * LLEN + l] = acc;
            }
        }
        __syncthreads();

        float msub = sce[0];
#pragma unroll
        for (int i = 1; i < 16; ++i) msub = fmaxf(msub, sce[i]);
        float newM = fmaxf(M, msub);
        float scale = __expf(M - newM);
        S *= scale;
        a.x *= scale; a.y *= scale; a.z *= scale; a.w *= scale;
        const float4* encb = (const float4*)enc + (size_t)lbase * BB * 256 + (size_t)b * 256 + tid;
#pragma unroll
        for (int i = 0; i < 16; ++i) {
            float w = __expf(sce[i] - newM);
            S += w;
            float4 v = __ldg(encb + (size_t)i * BB * 256);
            a.x += w * v.x; a.y += w * v.y; a.z += w * v.z; a.w += w * v.w;
        }
        M = newM;
        __syncthreads();
    }

    ((float4*)PCTX)[((size_t)b * 8 + chunk) * 256 + tid] = a;
    if (tid == 0) {
        MS[((size_t)b * 8 + chunk) * 2]     = M;
        MS[((size_t)b * 8 + chunk) * 2 + 1] = S;
    }
}

// combine 8 chunks: softmax stats, attention weights, context -> packed CINP (ctx half)
__global__ void __launch_bounds__(256) k_attn_combine(
    const float* __restrict__ E, const float* __restrict__ MS,
    const float* __restrict__ PCTX,
    float* __restrict__ packed, float* __restrict__ attn_out)
{
    __shared__ float sm[8], ss[8];
    __shared__ float sc[HH];
    const int b = blockIdx.x, tid = threadIdx.x;
    if (tid < 8) {
        sm[tid] = MS[((size_t)b * 8 + tid) * 2];
        ss[tid] = MS[((size_t)b * 8 + tid) * 2 + 1];
    }
    __syncthreads();
    float M = sm[0];
#pragma unroll
    for (int c = 1; c < 8; ++c) M = fmaxf(M, sm[c]);
    float S = 0.f;
#pragma unroll
    for (int c = 0; c < 8; ++c) S += ss[c] * __expf(sm[c] - M);
    const float inv = 1.f / S;

    float4 a = make_float4(0.f, 0.f, 0.f, 0.f);
#pragma unroll
    for (int c = 0; c < 8; ++c) {
        float w = __expf(sm[c] - M);
        float4 v = ((const float4*)PCTX)[((size_t)b * 8 + c) * 256 + tid];
        a.x += w * v.x; a.y += w * v.y; a.z += w * v.z; a.w += w * v.w;
    }
    a.x *= inv; a.y *= inv; a.z *= inv; a.w *= inv;
    ((float4*)sc)[tid] = a;

#pragma unroll
    for (int j = 0; j < 4; ++j) {
        int l = tid + j * 256;
        attn_out[(size_t)b * LLEN + l] = __expf(E[(size_t)b * LLEN + l] - M) * inv;
    }
    __syncthreads();

    const int ts = tid >> 2, tig = tid & 3;
    const int j0 = ts * 16 + tig * 2;
    uint32_t h01h, h01l, h23h, h23l;
    split2(make_float2(sc[j0], sc[j0 + 1]), h01h, h01l);
    split2(make_float2(sc[j0 + 8], sc[j0 + 9]), h23h, h23l);
    const int nf = b >> 3, lane = (b & 7) * 4 + tig;
    ((uint4*)packed)[((64 + ts) * 8 + nf) * 32 + lane] = make_uint4(h01h, h23h, h01l, h23l);
}

// ================= launcher =================
extern "C" void kernel_launch(void* const* d_in, const int* in_sizes, int n_in,
                              void* d_out, int out_size) {
    const int*   input_seq = (const int*)  d_in[0];
    const float* last_h    = (const float*)d_in[1];
    const float* enc       = (const float*)d_in[2];
    const float* emb       = (const float*)d_in[3];
    const float* W_ih      = (const float*)d_in[4];
    const float* W_hh      = (const float*)d_in[5];
    const float* b_ih      = (const float*)d_in[6];
    const float* b_hh      = (const float*)d_in[7];
    const float* W_concat  = (const float*)d_in[8];
    const float* b_concat  = (const float*)d_in[9];
    const float* W_out     = (const float*)d_in[10];
    const float* b_out     = (const float*)d_in[11];
    float* out = (float*)d_out;

    float* scratch = nullptr;
    cudaGetSymbolAddress((void**)&scratch, g_scratch);
    float* XP    = scratch;
    float* HP0   = scratch + 65536;
    float* HP1   = scratch + 131072;
    float* GX    = scratch + 196608;    // 4 slices x 196608
    float* GH    = scratch + 983040;    // 4 slices x 196608
    float* E     = scratch + 1769472;
    float* MS    = scratch + 1835008;
    float* PCTX  = scratch + 1836032;
    float* RNN   = scratch + 2360320;
    float* CINP  = scratch + 2425856;
    float* CC    = scratch + 2556928;   // 16 slices of 64x1024
    float* COUTP = scratch + 3605504;
    float* LOG   = scratch + 3671040;   // 2 slices of 64xVV

    float* out_logits = out;
    float* out_hidden = out + (size_t)BB * VV;
    float* out_attn   = out_hidden + (size_t)2 * BB * HH;

    cudaFuncSetAttribute(k_gemm, cudaFuncAttributeMaxDynamicSharedMemorySize, GEMM_SMEM);

    k_pack3<<<dim3(64, 3), 256>>>(emb, input_seq, last_h, last_h + (size_t)BB * HH,
                                  XP, HP0, HP1);

    // ---- GRU layer 0 (4 K-slices x 16 ksteps = K 1024) ----
    k_gemm<<<dim3(24, 2, 4), 256, GEMM_SMEM>>>(
        W_ih, (const uint4*)XP, GX, 3072, 1024, 16,
        W_hh, (const uint4*)HP0, GH);
    k_gates<<<dim3(64, 2), 128>>>(GX, GH, b_ih, b_hh, last_h,
                                  out_hidden, XP, nullptr);

    // ---- GRU layer 1 ----
    k_gemm<<<dim3(24, 2, 4), 256, GEMM_SMEM>>>(
        W_ih + (size_t)3072 * 1024, (const uint4*)XP, GX, 3072, 1024, 16,
        W_hh + (size_t)3072 * 1024, (const uint4*)HP1, GH);
    k_gates<<<dim3(64, 2), 128>>>(GX, GH, b_ih + 3072, b_hh + 3072,
                                  last_h + (size_t)BB * HH,
                                  out_hidden + (size_t)BB * HH, CINP, RNN);

    // ---- fused attention ----
    k_attn_fused<<<dim3(8, 64), 256>>>(RNN, enc, E, MS, PCTX);
    k_attn_combine<<<64, 256>>>(E, MS, PCTX, CINP, out_attn);

    // ---- concat GEMM (16 K-slices x 8 ksteps = K 2048) ----
    k_gemm<<<dim3(8, 1, 16), 256, GEMM_SMEM>>>(
        W_concat, (const uint4*)CINP, CC, 1024, 2048, 8,
        nullptr, nullptr, nullptr);
    k_pack_cout<<<64, 256>>>(CC, b_concat, COUTP);

    // ---- logits: split-K x2 (2 x 32 ksteps = K 1024) + reduce(+bias) ----
    k_gemm<<<dim3(393, 1, 2), 256, GEMM_SMEM>>>(
        W_out, (const uint4*)COUTP, LOG, VV, 1024, 32,
        nullptr, nullptr, nullptr);
    k_lred<<<dim3(197, 64), 256>>>(LOG, b_out, out_logits);

    (void)in_sizes; (void)n_in; (void)out_size;
}

// round 14
// speedup vs baseline: 1.2331x; 1.2331x over previous
#include <cuda_runtime.h>
#include <cuda_bf16.h>
#include <cstdint>

#define HH 1024
#define BB 64
#define LLEN 1024
#define VV 50257

// ---------------- split-bf16 helpers ----------------
__device__ __forceinline__ uint32_t pack_bf16x2(float lo, float hi) {
    uint32_t r;
    asm("cvt.rn.satfinite.bf16x2.f32 %0, %1, %2;" : "=r"(r) : "f"(hi), "f"(lo));
    return r;
}

__device__ __forceinline__ void split2(float2 v, uint32_t& hi, uint32_t& lo) {
    hi = pack_bf16x2(v.x, v.y);
    float lx = v.x - __uint_as_float(hi << 16);
    float ly = v.y - __uint_as_float(hi & 0xFFFF0000u);
    lo = pack_bf16x2(lx, ly);
}

__device__ __forceinline__ void mma16816(float* c,
                                         uint32_t a0, uint32_t a1, uint32_t a2, uint32_t a3,
                                         uint32_t b0, uint32_t b1) {
    asm volatile(
        "mma.sync.aligned.m16n8k16.row.col.f32.bf16.bf16.f32 "
        "{%0,%1,%2,%3}, {%4,%5,%6,%7}, {%8,%9}, {%0,%1,%2,%3};"
        : "+f"(c[0]), "+f"(c[1]), "+f"(c[2]), "+f"(c[3])
        : "r"(a0), "r"(a1), "r"(a2), "r"(a3), "r"(b0), "r"(b1));
}

// ---------------- cp.async helpers ----------------
__device__ __forceinline__ void cp_async16(uint32_t dst, const void* src, int szbytes) {
    asm volatile("cp.async.cg.shared.global [%0], [%1], 16, %2;"
                 :: "r"(dst), "l"(src), "r"(szbytes) : "memory");
}
__device__ __forceinline__ void cp_commit() {
    asm volatile("cp.async.commit_group;" ::: "memory");
}
__device__ __forceinline__ void cp_wait2() {
    asm volatile("cp.async.wait_group 2;" ::: "memory");
}

// ---------------- scratch layout (floats) ----------------
// XP 0 | HP0 65536 | HP1 131072 | GX 196608(4x196608) | GH 983040(4x196608)
// E 1769472(65536) | MS 1835008(1024) | PCTX 1836032(524288)
// RNN 2360320(65536) | CINP 2425856(131072) | CC 2556928(16x65536)
// COUTP 3605504(65536)  total 3671040
__device__ float g_scratch[3671040];

// ============ pack inputs: emb[idx] -> XP, last_h[0] -> HP0, last_h[1] -> HP1 ============
__global__ void __launch_bounds__(256) k_pack3(
    const float* __restrict__ emb, const int* __restrict__ idx,
    const float* __restrict__ h0, const float* __restrict__ h1,
    float* __restrict__ XP, float* __restrict__ HP0, float* __restrict__ HP1)
{
    int i = blockIdx.x * 256 + threadIdx.x;
    int lane = i & 31, nf = (i >> 5) & 7, t = i >> 8;
    int g = lane >> 2, tig = lane & 3;
    int n = nf * 8 + g;
    int k0 = t * 16 + tig * 2;
    const float* src;
    float* dst;
    if (blockIdx.y == 0)      { src = emb + (size_t)idx[n] * HH; dst = XP; }
    else if (blockIdx.y == 1) { src = h0 + (size_t)n * HH;       dst = HP0; }
    else                      { src = h1 + (size_t)n * HH;       dst = HP1; }
    float2 v0 = __ldg((const float2*)(src + k0));
    float2 v1 = __ldg((const float2*)(src + k0 + 8));
    uint32_t h0b, l0b, h1b, l1b;
    split2(v0, h0b, l0b);
    split2(v1, h1b, l1b);
    ((uint4*)dst)[i] = make_uint4(h0b, h1b, l0b, l1b);
}

// ============ sum 16 concat K-slices + bias + tanh, split-pack for W_out ============
__global__ void __launch_bounds__(256) k_pack_cout(
    const float* __restrict__ cc, const float* __restrict__ bias,
    float* __restrict__ dst)
{
    int i = blockIdx.x * 256 + threadIdx.x;
    int lane = i & 31, nf = (i >> 5) & 7, t = i >> 8;
    int g = lane >> 2, tig = lane & 3;
    int n = nf * 8 + g;
    int k0 = t * 16 + tig * 2;
    size_t base = (size_t)n * HH;
    float e0 = bias[k0], e1 = bias[k0 + 1], e2 = bias[k0 + 8], e3 = bias[k0 + 9];
#pragma unroll
    for (int z = 0; z < 16; ++z) {
        const float* p = cc + (size_t)z * 65536 + base;
        e0 += p[k0]; e1 += p[k0 + 1]; e2 += p[k0 + 8]; e3 += p[k0 + 9];
    }
    e0 = tanhf(e0); e1 = tanhf(e1); e2 = tanhf(e2); e3 = tanhf(e3);
    uint32_t h0, l0, h1, l1;
    split2(make_float2(e0, e1), h0, l0);
    split2(make_float2(e2, e3), h1, l1);
    ((uint4*)dst)[i] = make_uint4(h0, h1, l0, l1);
}

// ============ split-bf16 HMMA GEMM: cp.async 4-stage pipeline (R9 structure) ============
// 256 thr = 8 warps x 16 rows (128-row M tile). Stage: W 128x16 fp32 @80B row
// stride (10240B) + packed B 4096B = 14336B; 4 stages = 57344B smem.
// blockIdx.y==1 -> second param set; blockIdx.z -> K slice of tps ksteps.
// bias != nullptr: epilogue adds bias[m] (single-slice launches only).
#define STAGE_BYTES 14336
#define GEMM_SMEM   (4 * STAGE_BYTES)

__global__ void __launch_bounds__(256) k_gemm(
    const float* __restrict__ W, const uint4* __restrict__ P,
    float* __restrict__ out, int Nout, int K, int tps,
    const float* __restrict__ bias,
    const float* W2, const uint4* P2, float* out2)
{
    if (blockIdx.y == 1) { W = W2; P = P2; out = out2; }

    extern __shared__ char smem[];
    const uint32_t sbase = (uint32_t)__cvta_generic_to_shared(smem);

    const int tid = threadIdx.x;
    const int wid = tid >> 5;
    const int lane = tid & 31;
    const int g = lane >> 2;
    const int tig = lane & 3;

    const int m0 = blockIdx.x * 128;
    const int mA0 = m0 + wid * 16 + g, mA1 = mA0 + 8;
    const bool vA0 = mA0 < Nout, vA1 = mA1 < Nout;

    const int t0 = blockIdx.z * tps;
    const uint4* Pt = P + (size_t)t0 * 256;

    const int rowc0 = tid >> 2, colq = tid & 3;
    const int rowc1 = rowc0 + 64;
    const int mgc0 = m0 + rowc0, mgc1 = m0 + rowc1;
    const float* Wc0 = W + (size_t)(mgc0 < Nout ? mgc0 : 0) * K + colq * 4 + t0 * 16;
    const float* Wc1 = W + (size_t)(mgc1 < Nout ? mgc1 : 0) * K + colq * 4 + t0 * 16;
    const int sz0 = mgc0 < Nout ? 16 : 0;
    const int sz1 = mgc1 < Nout ? 16 : 0;
    const uint32_t dW0 = sbase + rowc0 * 80 + colq * 16;
    const uint32_t dW1 = sbase + rowc1 * 80 + colq * 16;
    const uint32_t dB  = sbase + 10240 + tid * 16;

    float acc[8][4];
#pragma unroll
    for (int nf = 0; nf < 8; ++nf)
#pragma unroll
        for (int j = 0; j < 4; ++j) acc[nf][j] = 0.f;

#define ISSUE_STAGE(t) do { \
    const int _s = (t) & 3; \
    const uint32_t _so = _s * STAGE_BYTES; \
    cp_async16(dW0 + _so, Wc0 + (size_t)(t) * 16, sz0); \
    cp_async16(dW1 + _so, Wc1 + (size_t)(t) * 16, sz1); \
    cp_async16(dB + _so, Pt + (size_t)(t) * 256 + tid, 16); \
} while (0)

    ISSUE_STAGE(0); cp_commit();
    if (1 < tps) ISSUE_STAGE(1);
    cp_commit();
    if (2 < tps) ISSUE_STAGE(2);
    cp_commit();

    for (int t = 0; t < tps; ++t) {
        cp_wait2();
        __syncthreads();            // stage t visible; stage t-1 fully consumed
        if (t + 3 < tps) ISSUE_STAGE(t + 3);
        cp_commit();

        const int s = t & 3;
        const char* sWs = smem + s * STAGE_BYTES;
        const uint4* sBs = (const uint4*)(smem + s * STAGE_BYTES + 10240);

        const int r0 = wid * 16 + g;
        const float2* pw0 = (const float2*)(sWs + r0 * 80 + tig * 8);
        const float2* pw1 = (const float2*)(sWs + (r0 + 8) * 80 + tig * 8);
        float2 w0 = pw0[0], w2 = pw0[4];
        float2 w1 = pw1[0], w3 = pw1[4];

        uint32_t ah0, al0, ah1, al1, ah2, al2, ah3, al3;
        split2(w0, ah0, al0); split2(w1, ah1, al1);
        split2(w2, ah2, al2); split2(w3, ah3, al3);

#pragma unroll
        for (int nf = 0; nf < 8; ++nf) {
            uint4 b = sBs[nf * 32 + lane];
            mma16816(acc[nf], ah0, ah1, ah2, ah3, b.x, b.y);   // Ahi*Bhi
            mma16816(acc[nf], ah0, ah1, ah2, ah3, b.z, b.w);   // Ahi*Blo
            mma16816(acc[nf], al0, al1, al2, al3, b.x, b.y);   // Alo*Bhi
        }
    }

    float* os = out + (size_t)blockIdx.z * 64 * Nout;
    const float bA0 = (bias && vA0) ? __ldg(bias + mA0) : 0.f;
    const float bA1 = (bias && vA1) ? __ldg(bias + mA1) : 0.f;
#pragma unroll
    for (int nf = 0; nf < 8; ++nf) {
        const int n0 = nf * 8 + tig * 2;
        if (vA0) {
            os[(size_t)n0 * Nout + mA0]       = acc[nf][0] + bA0;
            os[(size_t)(n0 + 1) * Nout + mA0] = acc[nf][1] + bA0;
        }
        if (vA1) {
            os[(size_t)n0 * Nout + mA1]       = acc[nf][2] + bA1;
            os[(size_t)(n0 + 1) * Nout + mA1] = acc[nf][3] + bA1;
        }
    }
#undef ISSUE_STAGE
}

// ============ GRU gates (4 K-slices), fused with next-stage packing ============
__global__ void __launch_bounds__(128) k_gates(
    const float* __restrict__ gx, const float* __restrict__ gh,
    const float* __restrict__ bih, const float* __restrict__ bhh,
    const float* __restrict__ hprev, float* __restrict__ out_hid,
    float* __restrict__ packed, float* __restrict__ rnn_fp32)
{
    const int b = blockIdx.x;
    const int t = threadIdx.x;
    const int ts = blockIdx.y * 32 + (t >> 2);
    const int tig = t & 3;
    const int j0 = ts * 16 + tig * 2;

    float h[4];
#pragma unroll
    for (int p = 0; p < 2; ++p) {
        const int j = j0 + p * 8;
        float2 gr = __ldg((const float2*)(bih + j));
        float2 gz = __ldg((const float2*)(bih + j + 1024));
        float2 gn = __ldg((const float2*)(bih + j + 2048));
        float2 hr = __ldg((const float2*)(bhh + j));
        float2 hz = __ldg((const float2*)(bhh + j + 1024));
        float2 hn = __ldg((const float2*)(bhh + j + 2048));
        const size_t o = (size_t)b * 3072 + j;
#pragma unroll
        for (int s = 0; s < 4; ++s) {
            const float* px = gx + (size_t)s * 196608 + o;
            const float* ph = gh + (size_t)s * 196608 + o;
            float2 v;
            v = __ldg((const float2*)px);          gr.x += v.x; gr.y += v.y;
            v = __ldg((const float2*)(px + 1024)); gz.x += v.x; gz.y += v.y;
            v = __ldg((const float2*)(px + 2048)); gn.x += v.x; gn.y += v.y;
            v = __ldg((const float2*)ph);          hr.x += v.x; hr.y += v.y;
            v = __ldg((const float2*)(ph + 1024)); hz.x += v.x; hz.y += v.y;
            v = __ldg((const float2*)(ph + 2048)); hn.x += v.x; hn.y += v.y;
        }
        float rx = 1.f / (1.f + __expf(-(gr.x + hr.x)));
        float ry = 1.f / (1.f + __expf(-(gr.y + hr.y)));
        float zx = 1.f / (1.f + __expf(-(gz.x + hz.x)));
        float zy = 1.f / (1.f + __expf(-(gz.y + hz.y)));
        float nx = tanhf(gn.x + rx * hn.x);
        float ny = tanhf(gn.y + ry * hn.y);
        float2 hp = __ldg((const float2*)(hprev + (size_t)b * 1024 + j));
        h[p * 2]     = (1.f - zx) * nx + zx * hp.x;
        h[p * 2 + 1] = (1.f - zy) * ny + zy * hp.y;
        out_hid[(size_t)b * 1024 + j]     = h[p * 2];
        out_hid[(size_t)b * 1024 + j + 1] = h[p * 2 + 1];
        if (rnn_fp32) {
            rnn_fp32[(size_t)b * 1024 + j]     = h[p * 2];
            rnn_fp32[(size_t)b * 1024 + j + 1] = h[p * 2 + 1];
        }
    }

    uint32_t h01h, h01l, h23h, h23l;
    split2(make_float2(h[0], h[1]), h01h, h01l);
    split2(make_float2(h[2], h[3]), h23h, h23l);
    const int nf = b >> 3, lane = (b & 7) * 4 + tig;
    ((uint4*)packed)[(ts * 8 + nf) * 32 + lane] = make_uint4(h01h, h23h, h01l, h23l);
}

// ============ fused attention: energy + online softmax + partial context ============
__global__ void __launch_bounds__(256) k_attn_fused(
    const float* __restrict__ rnn,
    const float* __restrict__ enc,
    float* __restrict__ E, float* __restrict__ MS, float* __restrict__ PCTX)
{
    __shared__ float sx[HH];
    __shared__ float sce[16];
    const int chunk = blockIdx.x, b = blockIdx.y;
    const int tid = threadIdx.x;
    const int wid = tid >> 5, lane = tid & 31;

    const float4* src = (const float4*)(rnn + (size_t)b * HH);
    for (int i = tid; i < HH / 4; i += 256)
        ((float4*)sx)[i] = src[i];
    __syncthreads();

    float M = -1e30f, S = 0.f;
    float4 a = make_float4(0.f, 0.f, 0.f, 0.f);
    const float4* sx4 = (const float4*)sx;

    for (int sub = 0; sub < 8; ++sub) {
        const int lbase = chunk * 128 + sub * 16;
#pragma unroll
        for (int j = 0; j < 2; ++j) {
            const int l = lbase + wid * 2 + j;
            const float4* e4 = (const float4*)(enc + ((size_t)l * BB + b) * HH);
            float acc = 0.f;
#pragma unroll
            for (int i = 0; i < 8; ++i) {
                float4 v = __ldg(e4 + lane + i * 32);
                float4 x = sx4[lane + i * 32];
                acc += v.x * x.x + v.y * x.y + v.z * x.z + v.w * x.w;
            }
#pragma unroll
            for (int o = 16; o; o >>= 1) acc += __shfl_xor_sync(0xffffffffu, acc, o);
            if (lane == 0) {
                sce[wid * 2 + j] = acc;
                E[(size_t)b * LLEN + l] = acc;
            }
        }
        __syncthreads();

        float msub = sce[0];
#pragma unroll
        for (int i = 1; i < 16; ++i) msub = fmaxf(msub, sce[i]);
        float newM = fmaxf(M, msub);
        float scale = __expf(M - newM);
        S *= scale;
        a.x *= scale; a.y *= scale; a.z *= scale; a.w *= scale;
        const float4* encb = (const float4*)enc + (size_t)lbase * BB * 256 + (size_t)b * 256 + tid;
#pragma unroll
        for (int i = 0; i < 16; ++i) {
            float w = __expf(sce[i] - newM);
            S += w;
            float4 v = __ldg(encb + (size_t)i * BB * 256);
            a.x += w * v.x; a.y += w * v.y; a.z += w * v.z; a.w += w * v.w;
        }
        M = newM;
        __syncthreads();
    }

    ((float4*)PCTX)[((size_t)b * 8 + chunk) * 256 + tid] = a;
    if (tid == 0) {
        MS[((size_t)b * 8 + chunk) * 2]     = M;
        MS[((size_t)b * 8 + chunk) * 2 + 1] = S;
    }
}

// combine 8 chunks: softmax stats, attention weights, context -> packed CINP (ctx half)
__global__ void __launch_bounds__(256) k_attn_combine(
    const float* __restrict__ E, const float* __restrict__ MS,
    const float* __restrict__ PCTX,
    float* __restrict__ packed, float* __restrict__ attn_out)
{
    __shared__ float sm[8], ss[8];
    __shared__ float sc[HH];
    const int b = blockIdx.x, tid = threadIdx.x;
    if (tid < 8) {
        sm[tid] = MS[((size_t)b * 8 + tid) * 2];
        ss[tid] = MS[((size_t)b * 8 + tid) * 2 + 1];
    }
    __syncthreads();
    float M = sm[0];
#pragma unroll
    for (int c = 1; c < 8; ++c) M = fmaxf(M, sm[c]);
    float S = 0.f;
#pragma unroll
    for (int c = 0; c < 8; ++c) S += ss[c] * __expf(sm[c] - M);
    const float inv = 1.f / S;

    float4 a = make_float4(0.f, 0.f, 0.f, 0.f);
#pragma unroll
    for (int c = 0; c < 8; ++c) {
        float w = __expf(sm[c] - M);
        float4 v = ((const float4*)PCTX)[((size_t)b * 8 + c) * 256 + tid];
        a.x += w * v.x; a.y += w * v.y; a.z += w * v.z; a.w += w * v.w;
    }
    a.x *= inv; a.y *= inv; a.z *= inv; a.w *= inv;
    ((float4*)sc)[tid] = a;

#pragma unroll
    for (int j = 0; j < 4; ++j) {
        int l = tid + j * 256;
        attn_out[(size_t)b * LLEN + l] = __expf(E[(size_t)b * LLEN + l] - M) * inv;
    }
    __syncthreads();

    const int ts = tid >> 2, tig = tid & 3;
    const int j0 = ts * 16 + tig * 2;
    uint32_t h01h, h01l, h23h, h23l;
    split2(make_float2(sc[j0], sc[j0 + 1]), h01h, h01l);
    split2(make_float2(sc[j0 + 8], sc[j0 + 9]), h23h, h23l);
    const int nf = b >> 3, lane = (b & 7) * 4 + tig;
    ((uint4*)packed)[((64 + ts) * 8 + nf) * 32 + lane] = make_uint4(h01h, h23h, h01l, h23l);
}

// ================= launcher =================
extern "C" void kernel_launch(void* const* d_in, const int* in_sizes, int n_in,
                              void* d_out, int out_size) {
    const int*   input_seq = (const int*)  d_in[0];
    const float* last_h    = (const float*)d_in[1];
    const float* enc       = (const float*)d_in[2];
    const float* emb       = (const float*)d_in[3];
    const float* W_ih      = (const float*)d_in[4];
    const float* W_hh      = (const float*)d_in[5];
    const float* b_ih      = (const float*)d_in[6];
    const float* b_hh      = (const float*)d_in[7];
    const float* W_concat  = (const float*)d_in[8];
    const float* b_concat  = (const float*)d_in[9];
    const float* W_out     = (const float*)d_in[10];
    const float* b_out     = (const float*)d_in[11];
    float* out = (float*)d_out;

    float* scratch = nullptr;
    cudaGetSymbolAddress((void**)&scratch, g_scratch);
    float* XP    = scratch;
    float* HP0   = scratch + 65536;
    float* HP1   = scratch + 131072;
    float* GX    = scratch + 196608;    // 4 slices x 196608
    float* GH    = scratch + 983040;    // 4 slices x 196608
    float* E     = scratch + 1769472;
    float* MS    = scratch + 1835008;
    float* PCTX  = scratch + 1836032;
    float* RNN   = scratch + 2360320;
    float* CINP  = scratch + 2425856;
    float* CC    = scratch + 2556928;   // 16 slices of 64x1024
    float* COUTP = scratch + 3605504;

    float* out_logits = out;
    float* out_hidden = out + (size_t)BB * VV;
    float* out_attn   = out_hidden + (size_t)2 * BB * HH;

    cudaFuncSetAttribute(k_gemm, cudaFuncAttributeMaxDynamicSharedMemorySize, GEMM_SMEM);

    k_pack3<<<dim3(64, 3), 256>>>(emb, input_seq, last_h, last_h + (size_t)BB * HH,
                                  XP, HP0, HP1);

    // ---- GRU layer 0 (4 K-slices x 16 ksteps = K 1024) ----
    k_gemm<<<dim3(24, 2, 4), 256, GEMM_SMEM>>>(
        W_ih, (const uint4*)XP, GX, 3072, 1024, 16, nullptr,
        W_hh, (const uint4*)HP0, GH);
    k_gates<<<dim3(64, 2), 128>>>(GX, GH, b_ih, b_hh, last_h,
                                  out_hidden, XP, nullptr);

    // ---- GRU layer 1 ----
    k_gemm<<<dim3(24, 2, 4), 256, GEMM_SMEM>>>(
        W_ih + (size_t)3072 * 1024, (const uint4*)XP, GX, 3072, 1024, 16, nullptr,
        W_hh + (size_t)3072 * 1024, (const uint4*)HP1, GH);
    k_gates<<<dim3(64, 2), 128>>>(GX, GH, b_ih + 3072, b_hh + 3072,
                                  last_h + (size_t)BB * HH,
                                  out_hidden + (size_t)BB * HH, CINP, RNN);

    // ---- fused attention ----
    k_attn_fused<<<dim3(8, 64), 256>>>(RNN, enc, E, MS, PCTX);
    k_attn_combine<<<64, 256>>>(E, MS, PCTX, CINP, out_attn);

    // ---- concat GEMM (16 K-slices x 8 ksteps = K 2048) ----
    k_gemm<<<dim3(8, 1, 16), 256, GEMM_SMEM>>>(
        W_concat, (const uint4*)CINP, CC, 1024, 2048, 8, nullptr,
        nullptr, nullptr, nullptr);
    k_pack_cout<<<64, 256>>>(CC, b_concat, COUTP);

    // ---- logits: single slice (tps=64), bias folded, direct to output ----
    k_gemm<<<dim3(393, 1, 1), 256, GEMM_SMEM>>>(
        W_out, (const uint4*)COUTP, out_logits, VV, 1024, 64, b_out,
        nullptr, nullptr, nullptr);

    (void)in_sizes; (void)n_in; (void)out_size;
}

// round 15
// speedup vs baseline: 1.3720x; 1.1126x over previous
#include <cuda_runtime.h>
#include <cuda_bf16.h>
#include <cuda_fp16.h>
#include <cstdint>

#define HH 1024
#define BB 64
#define LLEN 1024
#define VV 50257

// ---------------- split-bf16 helpers ----------------
__device__ __forceinline__ uint32_t pack_bf16x2(float lo, float hi) {
    uint32_t r;
    asm("cvt.rn.satfinite.bf16x2.f32 %0, %1, %2;" : "=r"(r) : "f"(hi), "f"(lo));
    return r;
}

__device__ __forceinline__ void split2(float2 v, uint32_t& hi, uint32_t& lo) {
    hi = pack_bf16x2(v.x, v.y);
    float lx = v.x - __uint_as_float(hi << 16);
    float ly = v.y - __uint_as_float(hi & 0xFFFF0000u);
    lo = pack_bf16x2(lx, ly);
}

// ---------------- split-fp16 helpers (logits GEMM) ----------------
__device__ __forceinline__ uint32_t pack_f16x2(float lo, float hi) {
    uint32_t r;
    asm("cvt.rn.f16x2.f32 %0, %1, %2;" : "=r"(r) : "f"(hi), "f"(lo));
    return r;
}

__device__ __forceinline__ void split2h(float2 v, uint32_t& hi, uint32_t& lo) {
    hi = pack_f16x2(v.x, v.y);
    __half2 h = *(__half2*)&hi;
    float2 b = __half22float2(h);
    lo = pack_f16x2(v.x - b.x, v.y - b.y);
}

__device__ __forceinline__ void mma16816(float* c,
                                         uint32_t a0, uint32_t a1, uint32_t a2, uint32_t a3,
                                         uint32_t b0, uint32_t b1) {
    asm volatile(
        "mma.sync.aligned.m16n8k16.row.col.f32.bf16.bf16.f32 "
        "{%0,%1,%2,%3}, {%4,%5,%6,%7}, {%8,%9}, {%0,%1,%2,%3};"
        : "+f"(c[0]), "+f"(c[1]), "+f"(c[2]), "+f"(c[3])
        : "r"(a0), "r"(a1), "r"(a2), "r"(a3), "r"(b0), "r"(b1));
}

__device__ __forceinline__ void mma16816h(float* c,
                                          uint32_t a0, uint32_t a1, uint32_t a2, uint32_t a3,
                                          uint32_t b0, uint32_t b1) {
    asm volatile(
        "mma.sync.aligned.m16n8k16.row.col.f32.f16.f16.f32 "
        "{%0,%1,%2,%3}, {%4,%5,%6,%7}, {%8,%9}, {%0,%1,%2,%3};"
        : "+f"(c[0]), "+f"(c[1]), "+f"(c[2]), "+f"(c[3])
        : "r"(a0), "r"(a1), "r"(a2), "r"(a3), "r"(b0), "r"(b1));
}

// ---------------- cp.async helpers ----------------
__device__ __forceinline__ void cp_async16(uint32_t dst, const void* src, int szbytes) {
    asm volatile("cp.async.cg.shared.global [%0], [%1], 16, %2;"
                 :: "r"(dst), "l"(src), "r"(szbytes) : "memory");
}
__device__ __forceinline__ void cp_commit() {
    asm volatile("cp.async.commit_group;" ::: "memory");
}
__device__ __forceinline__ void cp_wait2() {
    asm volatile("cp.async.wait_group 2;" ::: "memory");
}

// ---------------- scratch layout (floats) ----------------
// XP 0 | HP0 65536 | HP1 131072 | GX 196608(4x196608) | GH 983040(4x196608)
// E 1769472(65536) | MS 1835008(1024) | PCTX 1836032(524288)
// RNN 2360320(65536) | CINP 2425856(131072) | CC 2556928(16x65536)
// COUTP 3605504(32768 used)  total 3671040
__device__ float g_scratch[3671040];

// ============ pack inputs: emb[idx] -> XP, last_h[0] -> HP0, last_h[1] -> HP1 ============
__global__ void __launch_bounds__(256) k_pack3(
    const float* __restrict__ emb, const int* __restrict__ idx,
    const float* __restrict__ h0, const float* __restrict__ h1,
    float* __restrict__ XP, float* __restrict__ HP0, float* __restrict__ HP1)
{
    int i = blockIdx.x * 256 + threadIdx.x;
    int lane = i & 31, nf = (i >> 5) & 7, t = i >> 8;
    int g = lane >> 2, tig = lane & 3;
    int n = nf * 8 + g;
    int k0 = t * 16 + tig * 2;
    const float* src;
    float* dst;
    if (blockIdx.y == 0)      { src = emb + (size_t)idx[n] * HH; dst = XP; }
    else if (blockIdx.y == 1) { src = h0 + (size_t)n * HH;       dst = HP0; }
    else                      { src = h1 + (size_t)n * HH;       dst = HP1; }
    float2 v0 = __ldg((const float2*)(src + k0));
    float2 v1 = __ldg((const float2*)(src + k0 + 8));
    uint32_t h0b, l0b, h1b, l1b;
    split2(v0, h0b, l0b);
    split2(v1, h1b, l1b);
    ((uint4*)dst)[i] = make_uint4(h0b, h1b, l0b, l1b);
}

// ============ sum 16 concat K-slices + bias + tanh, fp16-pack for logits GEMM ============
__global__ void __launch_bounds__(256) k_pack_cout(
    const float* __restrict__ cc, const float* __restrict__ bias,
    uint2* __restrict__ dst)
{
    int i = blockIdx.x * 256 + threadIdx.x;
    int lane = i & 31, nf = (i >> 5) & 7, t = i >> 8;
    int g = lane >> 2, tig = lane & 3;
    int n = nf * 8 + g;
    int k0 = t * 16 + tig * 2;
    size_t base = (size_t)n * HH;
    float e0 = bias[k0], e1 = bias[k0 + 1], e2 = bias[k0 + 8], e3 = bias[k0 + 9];
#pragma unroll
    for (int z = 0; z < 16; ++z) {
        const float* p = cc + (size_t)z * 65536 + base;
        e0 += p[k0]; e1 += p[k0 + 1]; e2 += p[k0 + 8]; e3 += p[k0 + 9];
    }
    e0 = tanhf(e0); e1 = tanhf(e1); e2 = tanhf(e2); e3 = tanhf(e3);
    dst[i] = make_uint2(pack_f16x2(e0, e1), pack_f16x2(e2, e3));
}

// ============ split-bf16 HMMA GEMM: cp.async 4-stage pipeline (R9/R14 structure) ============
#define STAGE_BYTES 14336
#define GEMM_SMEM   (4 * STAGE_BYTES)

__global__ void __launch_bounds__(256) k_gemm(
    const float* __restrict__ W, const uint4* __restrict__ P,
    float* __restrict__ out, int Nout, int K, int tps,
    const float* W2, const uint4* P2, float* out2)
{
    if (blockIdx.y == 1) { W = W2; P = P2; out = out2; }

    extern __shared__ char smem[];
    const uint32_t sbase = (uint32_t)__cvta_generic_to_shared(smem);

    const int tid = threadIdx.x;
    const int wid = tid >> 5;
    const int lane = tid & 31;
    const int g = lane >> 2;
    const int tig = lane & 3;

    const int m0 = blockIdx.x * 128;
    const int mA0 = m0 + wid * 16 + g, mA1 = mA0 + 8;
    const bool vA0 = mA0 < Nout, vA1 = mA1 < Nout;

    const int t0 = blockIdx.z * tps;
    const uint4* Pt = P + (size_t)t0 * 256;

    const int rowc0 = tid >> 2, colq = tid & 3;
    const int rowc1 = rowc0 + 64;
    const int mgc0 = m0 + rowc0, mgc1 = m0 + rowc1;
    const float* Wc0 = W + (size_t)(mgc0 < Nout ? mgc0 : 0) * K + colq * 4 + t0 * 16;
    const float* Wc1 = W + (size_t)(mgc1 < Nout ? mgc1 : 0) * K + colq * 4 + t0 * 16;
    const int sz0 = mgc0 < Nout ? 16 : 0;
    const int sz1 = mgc1 < Nout ? 16 : 0;
    const uint32_t dW0 = sbase + rowc0 * 80 + colq * 16;
    const uint32_t dW1 = sbase + rowc1 * 80 + colq * 16;
    const uint32_t dB  = sbase + 10240 + tid * 16;

    float acc[8][4];
#pragma unroll
    for (int nf = 0; nf < 8; ++nf)
#pragma unroll
        for (int j = 0; j < 4; ++j) acc[nf][j] = 0.f;

#define ISSUE_STAGE(t) do { \
    const int _s = (t) & 3; \
    const uint32_t _so = _s * STAGE_BYTES; \
    cp_async16(dW0 + _so, Wc0 + (size_t)(t) * 16, sz0); \
    cp_async16(dW1 + _so, Wc1 + (size_t)(t) * 16, sz1); \
    cp_async16(dB + _so, Pt + (size_t)(t) * 256 + tid, 16); \
} while (0)

    ISSUE_STAGE(0); cp_commit();
    if (1 < tps) ISSUE_STAGE(1);
    cp_commit();
    if (2 < tps) ISSUE_STAGE(2);
    cp_commit();

    for (int t = 0; t < tps; ++t) {
        cp_wait2();
        __syncthreads();
        if (t + 3 < tps) ISSUE_STAGE(t + 3);
        cp_commit();

        const int s = t & 3;
        const char* sWs = smem + s * STAGE_BYTES;
        const uint4* sBs = (const uint4*)(smem + s * STAGE_BYTES + 10240);

        const int r0 = wid * 16 + g;
        const float2* pw0 = (const float2*)(sWs + r0 * 80 + tig * 8);
        const float2* pw1 = (const float2*)(sWs + (r0 + 8) * 80 + tig * 8);
        float2 w0 = pw0[0], w2 = pw0[4];
        float2 w1 = pw1[0], w3 = pw1[4];

        uint32_t ah0, al0, ah1, al1, ah2, al2, ah3, al3;
        split2(w0, ah0, al0); split2(w1, ah1, al1);
        split2(w2, ah2, al2); split2(w3, ah3, al3);

#pragma unroll
        for (int nf = 0; nf < 8; ++nf) {
            uint4 b = sBs[nf * 32 + lane];
            mma16816(acc[nf], ah0, ah1, ah2, ah3, b.x, b.y);
            mma16816(acc[nf], ah0, ah1, ah2, ah3, b.z, b.w);
            mma16816(acc[nf], al0, al1, al2, al3, b.x, b.y);
        }
    }

    float* os = out + (size_t)blockIdx.z * 64 * Nout;
#pragma unroll
    for (int nf = 0; nf < 8; ++nf) {
        const int n0 = nf * 8 + tig * 2;
        if (vA0) {
            os[(size_t)n0 * Nout + mA0]       = acc[nf][0];
            os[(size_t)(n0 + 1) * Nout + mA0] = acc[nf][1];
        }
        if (vA1) {
            os[(size_t)n0 * Nout + mA1]       = acc[nf][2];
            os[(size_t)(n0 + 1) * Nout + mA1] = acc[nf][3];
        }
    }
#undef ISSUE_STAGE
}

// ============ split-fp16 HMMA GEMM (logits): 2-term, B single-fp16 ============
// Stage: raw W 10240B + fp16 B 2048B = 12288B; 4 stages = 49152B smem.
// A split fp16 hi/lo in consumer; 16 MMAs per warp-kstep. bias folded.
#define STAGE16 12288
#define GEMM16_SMEM (4 * STAGE16)

__global__ void __launch_bounds__(256) k_gemm16(
    const float* __restrict__ W, const uint2* __restrict__ P,
    float* __restrict__ out, int Nout, int K, int tps,
    const float* __restrict__ bias)
{
    extern __shared__ char smem[];
    const uint32_t sbase = (uint32_t)__cvta_generic_to_shared(smem);

    const int tid = threadIdx.x;
    const int wid = tid >> 5;
    const int lane = tid & 31;
    const int g = lane >> 2;
    const int tig = lane & 3;

    const int m0 = blockIdx.x * 128;
    const int mA0 = m0 + wid * 16 + g, mA1 = mA0 + 8;
    const bool vA0 = mA0 < Nout, vA1 = mA1 < Nout;

    const uint2* Pt = P;   // single slice

    const int rowc0 = tid >> 2, colq = tid & 3;
    const int rowc1 = rowc0 + 64;
    const int mgc0 = m0 + rowc0, mgc1 = m0 + rowc1;
    const float* Wc0 = W + (size_t)(mgc0 < Nout ? mgc0 : 0) * K + colq * 4;
    const float* Wc1 = W + (size_t)(mgc1 < Nout ? mgc1 : 0) * K + colq * 4;
    const int sz0 = mgc0 < Nout ? 16 : 0;
    const int sz1 = mgc1 < Nout ? 16 : 0;
    const uint32_t dW0 = sbase + rowc0 * 80 + colq * 16;
    const uint32_t dW1 = sbase + rowc1 * 80 + colq * 16;
    const uint32_t dB  = sbase + 10240 + tid * 16;   // only tid<128 used

    float acc[8][4];
#pragma unroll
    for (int nf = 0; nf < 8; ++nf)
#pragma unroll
        for (int j = 0; j < 4; ++j) acc[nf][j] = 0.f;

#define ISSUE_STAGE16(t) do { \
    const int _s = (t) & 3; \
    const uint32_t _so = _s * STAGE16; \
    cp_async16(dW0 + _so, Wc0 + (size_t)(t) * 16, sz0); \
    cp_async16(dW1 + _so, Wc1 + (size_t)(t) * 16, sz1); \
    if (tid < 128) \
        cp_async16(dB + _so, (const char*)(Pt + (size_t)(t) * 256) + tid * 16, 16); \
} while (0)

    ISSUE_STAGE16(0); cp_commit();
    ISSUE_STAGE16(1); cp_commit();
    ISSUE_STAGE16(2); cp_commit();

    for (int t = 0; t < tps; ++t) {
        cp_wait2();
        __syncthreads();
        if (t + 3 < tps) ISSUE_STAGE16(t + 3);
        cp_commit();

        const int s = t & 3;
        const char* sWs = smem + s * STAGE16;
        const uint2* sBs = (const uint2*)(smem + s * STAGE16 + 10240);

        const int r0 = wid * 16 + g;
        const float2* pw0 = (const float2*)(sWs + r0 * 80 + tig * 8);
        const float2* pw1 = (const float2*)(sWs + (r0 + 8) * 80 + tig * 8);
        float2 w0 = pw0[0], w2 = pw0[4];
        float2 w1 = pw1[0], w3 = pw1[4];

        uint32_t ah0, al0, ah1, al1, ah2, al2, ah3, al3;
        split2h(w0, ah0, al0); split2h(w1, ah1, al1);
        split2h(w2, ah2, al2); split2h(w3, ah3, al3);

#pragma unroll
        for (int nf = 0; nf < 8; ++nf) {
            uint2 b = sBs[nf * 32 + lane];
            mma16816h(acc[nf], ah0, ah1, ah2, ah3, b.x, b.y);   // Ahi*B
            mma16816h(acc[nf], al0, al1, al2, al3, b.x, b.y);   // Alo*B
        }
    }

    const float bA0 = vA0 ? __ldg(bias + mA0) : 0.f;
    const float bA1 = vA1 ? __ldg(bias + mA1) : 0.f;
#pragma unroll
    for (int nf = 0; nf < 8; ++nf) {
        const int n0 = nf * 8 + tig * 2;
        if (vA0) {
            out[(size_t)n0 * Nout + mA0]       = acc[nf][0] + bA0;
            out[(size_t)(n0 + 1) * Nout + mA0] = acc[nf][1] + bA0;
        }
        if (vA1) {
            out[(size_t)n0 * Nout + mA1]       = acc[nf][2] + bA1;
            out[(size_t)(n0 + 1) * Nout + mA1] = acc[nf][3] + bA1;
        }
    }
#undef ISSUE_STAGE16
}

// ============ GRU gates (4 K-slices), fused with next-stage packing ============
__global__ void __launch_bounds__(128) k_gates(
    const float* __restrict__ gx, const float* __restrict__ gh,
    const float* __restrict__ bih, const float* __restrict__ bhh,
    const float* __restrict__ hprev, float* __restrict__ out_hid,
    float* __restrict__ packed, float* __restrict__ rnn_fp32)
{
    const int b = blockIdx.x;
    const int t = threadIdx.x;
    const int ts = blockIdx.y * 32 + (t >> 2);
    const int tig = t & 3;
    const int j0 = ts * 16 + tig * 2;

    float h[4];
#pragma unroll
    for (int p = 0; p < 2; ++p) {
        const int j = j0 + p * 8;
        float2 gr = __ldg((const float2*)(bih + j));
        float2 gz = __ldg((const float2*)(bih + j + 1024));
        float2 gn = __ldg((const float2*)(bih + j + 2048));
        float2 hr = __ldg((const float2*)(bhh + j));
        float2 hz = __ldg((const float2*)(bhh + j + 1024));
        float2 hn = __ldg((const float2*)(bhh + j + 2048));
        const size_t o = (size_t)b * 3072 + j;
#pragma unroll
        for (int s = 0; s < 4; ++s) {
            const float* px = gx + (size_t)s * 196608 + o;
            const float* ph = gh + (size_t)s * 196608 + o;
            float2 v;
            v = __ldg((const float2*)px);          gr.x += v.x; gr.y += v.y;
            v = __ldg((const float2*)(px + 1024)); gz.x += v.x; gz.y += v.y;
            v = __ldg((const float2*)(px + 2048)); gn.x += v.x; gn.y += v.y;
            v = __ldg((const float2*)ph);          hr.x += v.x; hr.y += v.y;
            v = __ldg((const float2*)(ph + 1024)); hz.x += v.x; hz.y += v.y;
            v = __ldg((const float2*)(ph + 2048)); hn.x += v.x; hn.y += v.y;
        }
        float rx = 1.f / (1.f + __expf(-(gr.x + hr.x)));
        float ry = 1.f / (1.f + __expf(-(gr.y + hr.y)));
        float zx = 1.f / (1.f + __expf(-(gz.x + hz.x)));
        float zy = 1.f / (1.f + __expf(-(gz.y + hz.y)));
        float nx = tanhf(gn.x + rx * hn.x);
        float ny = tanhf(gn.y + ry * hn.y);
        float2 hp = __ldg((const float2*)(hprev + (size_t)b * 1024 + j));
        h[p * 2]     = (1.f - zx) * nx + zx * hp.x;
        h[p * 2 + 1] = (1.f - zy) * ny + zy * hp.y;
        out_hid[(size_t)b * 1024 + j]     = h[p * 2];
        out_hid[(size_t)b * 1024 + j + 1] = h[p * 2 + 1];
        if (rnn_fp32) {
            rnn_fp32[(size_t)b * 1024 + j]     = h[p * 2];
            rnn_fp32[(size_t)b * 1024 + j + 1] = h[p * 2 + 1];
        }
    }

    uint32_t h01h, h01l, h23h, h23l;
    split2(make_float2(h[0], h[1]), h01h, h01l);
    split2(make_float2(h[2], h[3]), h23h, h23l);
    const int nf = b >> 3, lane = (b & 7) * 4 + tig;
    ((uint4*)packed)[(ts * 8 + nf) * 32 + lane] = make_uint4(h01h, h23h, h01l, h23l);
}

// ============ fused attention: energy + online softmax + partial context ============
__global__ void __launch_bounds__(256) k_attn_fused(
    const float* __restrict__ rnn,
    const float* __restrict__ enc,
    float* __restrict__ E, float* __restrict__ MS, float* __restrict__ PCTX)
{
    __shared__ float sx[HH];
    __shared__ float sce[16];
    const int chunk = blockIdx.x, b = blockIdx.y;
    const int tid = threadIdx.x;
    const int wid = tid >> 5, lane = tid & 31;

    const float4* src = (const float4*)(rnn + (size_t)b * HH);
    for (int i = tid; i < HH / 4; i += 256)
        ((float4*)sx)[i] = src[i];
    __syncthreads();

    float M = -1e30f, S = 0.f;
    float4 a = make_float4(0.f, 0.f, 0.f, 0.f);
    const float4* sx4 = (const float4*)sx;

    for (int sub = 0; sub < 8; ++sub) {
        const int lbase = chunk * 128 + sub * 16;
#pragma unroll
        for (int j = 0; j < 2; ++j) {
            const int l = lbase + wid * 2 + j;
            const float4* e4 = (const float4*)(enc + ((size_t)l * BB + b) * HH);
            float acc = 0.f;
#pragma unroll
            for (int i = 0; i < 8; ++i) {
                float4 v = __ldg(e4 + lane + i * 32);
                float4 x = sx4[lane + i * 32];
                acc += v.x * x.x + v.y * x.y + v.z * x.z + v.w * x.w;
            }
#pragma unroll
            for (int o = 16; o; o >>= 1) acc += __shfl_xor_sync(0xffffffffu, acc, o);
            if (lane == 0) {
                sce[wid * 2 + j] = acc;
                E[(size_t)b * LLEN + l] = acc;
            }
        }
        __syncthreads();

        float msub = sce[0];
#pragma unroll
        for (int i = 1; i < 16; ++i) msub = fmaxf(msub, sce[i]);
        float newM = fmaxf(M, msub);
        float scale = __expf(M - newM);
        S *= scale;
        a.x *= scale; a.y *= scale; a.z *= scale; a.w *= scale;
        const float4* encb = (const float4*)enc + (size_t)lbase * BB * 256 + (size_t)b * 256 + tid;
#pragma unroll
        for (int i = 0; i < 16; ++i) {
            float w = __expf(sce[i] - newM);
            S += w;
            float4 v = __ldg(encb + (size_t)i * BB * 256);
            a.x += w * v.x; a.y += w * v.y; a.z += w * v.z; a.w += w * v.w;
        }
        M = newM;
        __syncthreads();
    }

    ((float4*)PCTX)[((size_t)b * 8 + chunk) * 256 + tid] = a;
    if (tid == 0) {
        MS[((size_t)b * 8 + chunk) * 2]     = M;
        MS[((size_t)b * 8 + chunk) * 2 + 1] = S;
    }
}

// combine 8 chunks: softmax stats, attention weights, context -> packed CINP (ctx half)
__global__ void __launch_bounds__(256) k_attn_combine(
    const float* __restrict__ E, const float* __restrict__ MS,
    const float* __restrict__ PCTX,
    float* __restrict__ packed, float* __restrict__ attn_out)
{
    __shared__ float sm[8], ss[8];
    __shared__ float sc[HH];
    const int b = blockIdx.x, tid = threadIdx.x;
    if (tid < 8) {
        sm[tid] = MS[((size_t)b * 8 + tid) * 2];
        ss[tid] = MS[((size_t)b * 8 + tid) * 2 + 1];
    }
    __syncthreads();
    float M = sm[0];
#pragma unroll
    for (int c = 1; c < 8; ++c) M = fmaxf(M, sm[c]);
    float S = 0.f;
#pragma unroll
    for (int c = 0; c < 8; ++c) S += ss[c] * __expf(sm[c] - M);
    const float inv = 1.f / S;

    float4 a = make_float4(0.f, 0.f, 0.f, 0.f);
#pragma unroll
    for (int c = 0; c < 8; ++c) {
        float w = __expf(sm[c] - M);
        float4 v = ((const float4*)PCTX)[((size_t)b * 8 + c) * 256 + tid];
        a.x += w * v.x; a.y += w * v.y; a.z += w * v.z; a.w += w * v.w;
    }
    a.x *= inv; a.y *= inv; a.z *= inv; a.w *= inv;
    ((float4*)sc)[tid] = a;

#pragma unroll
    for (int j = 0; j < 4; ++j) {
        int l = tid + j * 256;
        attn_out[(size_t)b * LLEN + l] = __expf(E[(size_t)b * LLEN + l] - M) * inv;
    }
    __syncthreads();

    const int ts = tid >> 2, tig = tid & 3;
    const int j0 = ts * 16 + tig * 2;
    uint32_t h01h, h01l, h23h, h23l;
    split2(make_float2(sc[j0], sc[j0 + 1]), h01h, h01l);
    split2(make_float2(sc[j0 + 8], sc[j0 + 9]), h23h, h23l);
    const int nf = b >> 3, lane = (b & 7) * 4 + tig;
    ((uint4*)packed)[((64 + ts) * 8 + nf) * 32 + lane] = make_uint4(h01h, h23h, h01l, h23l);
}

// ================= launcher =================
extern "C" void kernel_launch(void* const* d_in, const int* in_sizes, int n_in,
                              void* d_out, int out_size) {
    const int*   input_seq = (const int*)  d_in[0];
    const float* last_h    = (const float*)d_in[1];
    const float* enc       = (const float*)d_in[2];
    const float* emb       = (const float*)d_in[3];
    const float* W_ih      = (const float*)d_in[4];
    const float* W_hh      = (const float*)d_in[5];
    const float* b_ih      = (const float*)d_in[6];
    const float* b_hh      = (const float*)d_in[7];
    const float* W_concat  = (const float*)d_in[8];
    const float* b_concat  = (const float*)d_in[9];
    const float* W_out     = (const float*)d_in[10];
    const float* b_out     = (const float*)d_in[11];
    float* out = (float*)d_out;

    float* scratch = nullptr;
    cudaGetSymbolAddress((void**)&scratch, g_scratch);
    float* XP    = scratch;
    float* HP0   = scratch + 65536;
    float* HP1   = scratch + 131072;
    float* GX    = scratch + 196608;    // 4 slices x 196608
    float* GH    = scratch + 983040;    // 4 slices x 196608
    float* E     = scratch + 1769472;
    float* MS    = scratch + 1835008;
    float* PCTX  = scratch + 1836032;
    float* RNN   = scratch + 2360320;
    float* CINP  = scratch + 2425856;
    float* CC    = scratch + 2556928;   // 16 slices of 64x1024
    float* COUTP = scratch + 3605504;   // fp16-packed: 32768 floats used

    float* out_logits = out;
    float* out_hidden = out + (size_t)BB * VV;
    float* out_attn   = out_hidden + (size_t)2 * BB * HH;

    cudaFuncSetAttribute(k_gemm, cudaFuncAttributeMaxDynamicSharedMemorySize, GEMM_SMEM);
    cudaFuncSetAttribute(k_gemm16, cudaFuncAttributeMaxDynamicSharedMemorySize, GEMM16_SMEM);

    k_pack3<<<dim3(64, 3), 256>>>(emb, input_seq, last_h, last_h + (size_t)BB * HH,
                                  XP, HP0, HP1);

    // ---- GRU layer 0 (4 K-slices x 16 ksteps = K 1024) ----
    k_gemm<<<dim3(24, 2, 4), 256, GEMM_SMEM>>>(
        W_ih, (const uint4*)XP, GX, 3072, 1024, 16,
        W_hh, (const uint4*)HP0, GH);
    k_gates<<<dim3(64, 2), 128>>>(GX, GH, b_ih, b_hh, last_h,
                                  out_hidden, XP, nullptr);

    // ---- GRU layer 1 ----
    k_gemm<<<dim3(24, 2, 4), 256, GEMM_SMEM>>>(
        W_ih + (size_t)3072 * 1024, (const uint4*)XP, GX, 3072, 1024, 16,
        W_hh + (size_t)3072 * 1024, (const uint4*)HP1, GH);
    k_gates<<<dim3(64, 2), 128>>>(GX, GH, b_ih + 3072, b_hh + 3072,
                                  last_h + (size_t)BB * HH,
                                  out_hidden + (size_t)BB * HH, CINP, RNN);

    // ---- fused attention ----
    k_attn_fused<<<dim3(8, 64), 256>>>(RNN, enc, E, MS, PCTX);
    k_attn_combine<<<64, 256>>>(E, MS, PCTX, CINP, out_attn);

    // ---- concat GEMM (16 K-slices x 8 ksteps = K 2048) ----
    k_gemm<<<dim3(8, 1, 16), 256, GEMM_SMEM>>>(
        W_concat, (const uint4*)CINP, CC, 1024, 2048, 8,
        nullptr, nullptr, nullptr);
    k_pack_cout<<<64, 256>>>(CC, b_concat, (uint2*)COUTP);

    // ---- logits: split-fp16 2-term, single slice, bias folded, direct output ----
    k_gemm16<<<dim3(393, 1, 1), 256, GEMM16_SMEM>>>(
        W_out, (const uint2*)COUTP, out_logits, VV, 1024, 64, b_out);

    (void)in_sizes; (void)n_in; (void)out_size;
}

// round 16
// speedup vs baseline: 1.4797x; 1.0785x over previous
#include <cuda_runtime.h>
#include <cuda_bf16.h>
#include <cuda_fp16.h>
#include <cstdint>

#define HH 1024
#define BB 64
#define LLEN 1024
#define VV 50257

// ---------------- fp16 helpers ----------------
__device__ __forceinline__ uint32_t pack_f16x2(float lo, float hi) {
    uint32_t r;
    asm("cvt.rn.f16x2.f32 %0, %1, %2;" : "=r"(r) : "f"(hi), "f"(lo));
    return r;
}

// exact W split: hi fp16 + residual lo fp16 (covers fp32 to ~2^-22)
__device__ __forceinline__ void split2h(float2 v, uint32_t& hi, uint32_t& lo) {
    hi = pack_f16x2(v.x, v.y);
    __half2 h = *(__half2*)&hi;
    float2 b = __half22float2(h);
    lo = pack_f16x2(v.x - b.x, v.y - b.y);
}

__device__ __forceinline__ void mma16816h(float* c,
                                          uint32_t a0, uint32_t a1, uint32_t a2, uint32_t a3,
                                          uint32_t b0, uint32_t b1) {
    asm volatile(
        "mma.sync.aligned.m16n8k16.row.col.f32.f16.f16.f32 "
        "{%0,%1,%2,%3}, {%4,%5,%6,%7}, {%8,%9}, {%0,%1,%2,%3};"
        : "+f"(c[0]), "+f"(c[1]), "+f"(c[2]), "+f"(c[3])
        : "r"(a0), "r"(a1), "r"(a2), "r"(a3), "r"(b0), "r"(b1));
}

// ---------------- cp.async helpers ----------------
__device__ __forceinline__ void cp_async16(uint32_t dst, const void* src, int szbytes) {
    asm volatile("cp.async.cg.shared.global [%0], [%1], 16, %2;"
                 :: "r"(dst), "l"(src), "r"(szbytes) : "memory");
}
__device__ __forceinline__ void cp_commit() {
    asm volatile("cp.async.commit_group;" ::: "memory");
}
__device__ __forceinline__ void cp_wait2() {
    asm volatile("cp.async.wait_group 2;" ::: "memory");
}

// ---------------- scratch layout (floats) ----------------
// XP 0 | HP0 65536 | HP1 131072 | GX 196608(4x196608) | GH 983040(4x196608)
// E 1769472(65536) | MS 1835008(1024) | PCTX 1836032(524288)
// RNN 2360320(65536) | CINP 2425856(131072) | CC 2556928(16x65536)
// COUTP 3605504(32768 used)  total 3671040
__device__ float g_scratch[3671040];

// ============ pack inputs (fp16 B fragments): emb[idx]->XP, last_h->HP0/HP1 ============
__global__ void __launch_bounds__(256) k_pack3(
    const float* __restrict__ emb, const int* __restrict__ idx,
    const float* __restrict__ h0, const float* __restrict__ h1,
    uint2* __restrict__ XP, uint2* __restrict__ HP0, uint2* __restrict__ HP1)
{
    int i = blockIdx.x * 256 + threadIdx.x;
    int lane = i & 31, nf = (i >> 5) & 7, t = i >> 8;
    int g = lane >> 2, tig = lane & 3;
    int n = nf * 8 + g;
    int k0 = t * 16 + tig * 2;
    const float* src;
    uint2* dst;
    if (blockIdx.y == 0)      { src = emb + (size_t)idx[n] * HH; dst = XP; }
    else if (blockIdx.y == 1) { src = h0 + (size_t)n * HH;       dst = HP0; }
    else                      { src = h1 + (size_t)n * HH;       dst = HP1; }
    float2 v0 = __ldg((const float2*)(src + k0));
    float2 v1 = __ldg((const float2*)(src + k0 + 8));
    dst[i] = make_uint2(pack_f16x2(v0.x, v0.y), pack_f16x2(v1.x, v1.y));
}

// ============ sum 16 concat K-slices + bias + tanh, fp16-pack for logits GEMM ============
__global__ void __launch_bounds__(256) k_pack_cout(
    const float* __restrict__ cc, const float* __restrict__ bias,
    uint2* __restrict__ dst)
{
    int i = blockIdx.x * 256 + threadIdx.x;
    int lane = i & 31, nf = (i >> 5) & 7, t = i >> 8;
    int g = lane >> 2, tig = lane & 3;
    int n = nf * 8 + g;
    int k0 = t * 16 + tig * 2;
    size_t base = (size_t)n * HH;
    float e0 = bias[k0], e1 = bias[k0 + 1], e2 = bias[k0 + 8], e3 = bias[k0 + 9];
#pragma unroll
    for (int z = 0; z < 16; ++z) {
        const float* p = cc + (size_t)z * 65536 + base;
        e0 += p[k0]; e1 += p[k0 + 1]; e2 += p[k0 + 8]; e3 += p[k0 + 9];
    }
    e0 = tanhf(e0); e1 = tanhf(e1); e2 = tanhf(e2); e3 = tanhf(e3);
    dst[i] = make_uint2(pack_f16x2(e0, e1), pack_f16x2(e2, e3));
}

// ============ unified split-fp16 HMMA GEMM: 2-term, cp.async 4-stage ring ============
// 256 thr = 8 warps x 16 rows (128-row M tile). Stage: raw W fp32 10240B (80B row
// stride) + fp16 B 2048B = 12288B; 4 stages = 49152B smem.
// blockIdx.y==1 -> second param set; blockIdx.z -> K slice of tps ksteps.
// bias != nullptr -> epilogue adds bias[m] (single-slice launches only).
#define STAGE_BYTES 12288
#define GEMM_SMEM   (4 * STAGE_BYTES)

__global__ void __launch_bounds__(256) k_gemm(
    const float* __restrict__ W, const uint2* __restrict__ P,
    float* __restrict__ out, int Nout, int K, int tps,
    const float* __restrict__ bias,
    const float* W2, const uint2* P2, float* out2)
{
    if (blockIdx.y == 1) { W = W2; P = P2; out = out2; }

    extern __shared__ char smem[];
    const uint32_t sbase = (uint32_t)__cvta_generic_to_shared(smem);

    const int tid = threadIdx.x;
    const int wid = tid >> 5;
    const int lane = tid & 31;
    const int g = lane >> 2;
    const int tig = lane & 3;

    const int m0 = blockIdx.x * 128;
    const int mA0 = m0 + wid * 16 + g, mA1 = mA0 + 8;
    const bool vA0 = mA0 < Nout, vA1 = mA1 < Nout;

    const int t0 = blockIdx.z * tps;
    const uint2* Pt = P + (size_t)t0 * 256;

    const int rowc0 = tid >> 2, colq = tid & 3;
    const int rowc1 = rowc0 + 64;
    const int mgc0 = m0 + rowc0, mgc1 = m0 + rowc1;
    const float* Wc0 = W + (size_t)(mgc0 < Nout ? mgc0 : 0) * K + colq * 4 + t0 * 16;
    const float* Wc1 = W + (size_t)(mgc1 < Nout ? mgc1 : 0) * K + colq * 4 + t0 * 16;
    const int sz0 = mgc0 < Nout ? 16 : 0;
    const int sz1 = mgc1 < Nout ? 16 : 0;
    const uint32_t dW0 = sbase + rowc0 * 80 + colq * 16;
    const uint32_t dW1 = sbase + rowc1 * 80 + colq * 16;
    const uint32_t dB  = sbase + 10240 + tid * 16;   // only tid<128 used

    float acc[8][4];
#pragma unroll
    for (int nf = 0; nf < 8; ++nf)
#pragma unroll
        for (int j = 0; j < 4; ++j) acc[nf][j] = 0.f;

#define ISSUE_STAGE(t) do { \
    const int _s = (t) & 3; \
    const uint32_t _so = _s * STAGE_BYTES; \
    cp_async16(dW0 + _so, Wc0 + (size_t)(t) * 16, sz0); \
    cp_async16(dW1 + _so, Wc1 + (size_t)(t) * 16, sz1); \
    if (tid < 128) \
        cp_async16(dB + _so, (const char*)(Pt + (size_t)(t) * 256) + tid * 16, 16); \
} while (0)

    ISSUE_STAGE(0); cp_commit();
    if (1 < tps) ISSUE_STAGE(1);
    cp_commit();
    if (2 < tps) ISSUE_STAGE(2);
    cp_commit();

    for (int t = 0; t < tps; ++t) {
        cp_wait2();
        __syncthreads();            // stage t visible; stage t-1 fully consumed
        if (t + 3 < tps) ISSUE_STAGE(t + 3);
        cp_commit();

        const int s = t & 3;
        const char* sWs = smem + s * STAGE_BYTES;
        const uint2* sBs = (const uint2*)(smem + s * STAGE_BYTES + 10240);

        const int r0 = wid * 16 + g;
        const float2* pw0 = (const float2*)(sWs + r0 * 80 + tig * 8);
        const float2* pw1 = (const float2*)(sWs + (r0 + 8) * 80 + tig * 8);
        float2 w0 = pw0[0], w2 = pw0[4];
        float2 w1 = pw1[0], w3 = pw1[4];

        uint32_t ah0, al0, ah1, al1, ah2, al2, ah3, al3;
        split2h(w0, ah0, al0); split2h(w1, ah1, al1);
        split2h(w2, ah2, al2); split2h(w3, ah3, al3);

#pragma unroll
        for (int nf = 0; nf < 8; ++nf) {
            uint2 b = sBs[nf * 32 + lane];
            mma16816h(acc[nf], ah0, ah1, ah2, ah3, b.x, b.y);   // Whi * B
            mma16816h(acc[nf], al0, al1, al2, al3, b.x, b.y);   // Wlo * B
        }
    }

    float* os = out + (size_t)blockIdx.z * 64 * Nout;
    const float bA0 = (bias && vA0) ? __ldg(bias + mA0) : 0.f;
    const float bA1 = (bias && vA1) ? __ldg(bias + mA1) : 0.f;
#pragma unroll
    for (int nf = 0; nf < 8; ++nf) {
        const int n0 = nf * 8 + tig * 2;
        if (vA0) {
            os[(size_t)n0 * Nout + mA0]       = acc[nf][0] + bA0;
            os[(size_t)(n0 + 1) * Nout + mA0] = acc[nf][1] + bA0;
        }
        if (vA1) {
            os[(size_t)n0 * Nout + mA1]       = acc[nf][2] + bA1;
            os[(size_t)(n0 + 1) * Nout + mA1] = acc[nf][3] + bA1;
        }
    }
#undef ISSUE_STAGE
}

// ============ GRU gates (4 K-slices), fused with fp16 packing ============
__global__ void __launch_bounds__(128) k_gates(
    const float* __restrict__ gx, const float* __restrict__ gh,
    const float* __restrict__ bih, const float* __restrict__ bhh,
    const float* __restrict__ hprev, float* __restrict__ out_hid,
    uint2* __restrict__ packed, float* __restrict__ rnn_fp32)
{
    const int b = blockIdx.x;
    const int t = threadIdx.x;
    const int ts = blockIdx.y * 32 + (t >> 2);
    const int tig = t & 3;
    const int j0 = ts * 16 + tig * 2;

    float h[4];
#pragma unroll
    for (int p = 0; p < 2; ++p) {
        const int j = j0 + p * 8;
        float2 gr = __ldg((const float2*)(bih + j));
        float2 gz = __ldg((const float2*)(bih + j + 1024));
        float2 gn = __ldg((const float2*)(bih + j + 2048));
        float2 hr = __ldg((const float2*)(bhh + j));
        float2 hz = __ldg((const float2*)(bhh + j + 1024));
        float2 hn = __ldg((const float2*)(bhh + j + 2048));
        const size_t o = (size_t)b * 3072 + j;
#pragma unroll
        for (int s = 0; s < 4; ++s) {
            const float* px = gx + (size_t)s * 196608 + o;
            const float* ph = gh + (size_t)s * 196608 + o;
            float2 v;
            v = __ldg((const float2*)px);          gr.x += v.x; gr.y += v.y;
            v = __ldg((const float2*)(px + 1024)); gz.x += v.x; gz.y += v.y;
            v = __ldg((const float2*)(px + 2048)); gn.x += v.x; gn.y += v.y;
            v = __ldg((const float2*)ph);          hr.x += v.x; hr.y += v.y;
            v = __ldg((const float2*)(ph + 1024)); hz.x += v.x; hz.y += v.y;
            v = __ldg((const float2*)(ph + 2048)); hn.x += v.x; hn.y += v.y;
        }
        float rx = 1.f / (1.f + __expf(-(gr.x + hr.x)));
        float ry = 1.f / (1.f + __expf(-(gr.y + hr.y)));
        float zx = 1.f / (1.f + __expf(-(gz.x + hz.x)));
        float zy = 1.f / (1.f + __expf(-(gz.y + hz.y)));
        float nx = tanhf(gn.x + rx * hn.x);
        float ny = tanhf(gn.y + ry * hn.y);
        float2 hp = __ldg((const float2*)(hprev + (size_t)b * 1024 + j));
        h[p * 2]     = (1.f - zx) * nx + zx * hp.x;
        h[p * 2 + 1] = (1.f - zy) * ny + zy * hp.y;
        out_hid[(size_t)b * 1024 + j]     = h[p * 2];
        out_hid[(size_t)b * 1024 + j + 1] = h[p * 2 + 1];
        if (rnn_fp32) {
            rnn_fp32[(size_t)b * 1024 + j]     = h[p * 2];
            rnn_fp32[(size_t)b * 1024 + j + 1] = h[p * 2 + 1];
        }
    }

    const int nf = b >> 3, lane = (b & 7) * 4 + tig;
    packed[(ts * 8 + nf) * 32 + lane] =
        make_uint2(pack_f16x2(h[0], h[1]), pack_f16x2(h[2], h[3]));
}

// ============ fused attention: energy + online softmax + partial context ============
__global__ void __launch_bounds__(256) k_attn_fused(
    const float* __restrict__ rnn,
    const float* __restrict__ enc,
    float* __restrict__ E, float* __restrict__ MS, float* __restrict__ PCTX)
{
    __shared__ float sx[HH];
    __shared__ float sce[16];
    const int chunk = blockIdx.x, b = blockIdx.y;
    const int tid = threadIdx.x;
    const int wid = tid >> 5, lane = tid & 31;

    const float4* src = (const float4*)(rnn + (size_t)b * HH);
    for (int i = tid; i < HH / 4; i += 256)
        ((float4*)sx)[i] = src[i];
    __syncthreads();

    float M = -1e30f, S = 0.f;
    float4 a = make_float4(0.f, 0.f, 0.f, 0.f);
    const float4* sx4 = (const float4*)sx;

    for (int sub = 0; sub < 8; ++sub) {
        const int lbase = chunk * 128 + sub * 16;
#pragma unroll
        for (int j = 0; j < 2; ++j) {
            const int l = lbase + wid * 2 + j;
            const float4* e4 = (const float4*)(enc + ((size_t)l * BB + b) * HH);
            float acc = 0.f;
#pragma unroll
            for (int i = 0; i < 8; ++i) {
                float4 v = __ldg(e4 + lane + i * 32);
                float4 x = sx4[lane + i * 32];
                acc += v.x * x.x + v.y * x.y + v.z * x.z + v.w * x.w;
            }
#pragma unroll
            for (int o = 16; o; o >>= 1) acc += __shfl_xor_sync(0xffffffffu, acc, o);
            if (lane == 0) {
                sce[wid * 2 + j] = acc;
                E[(size_t)b * LLEN + l] = acc;
            }
        }
        __syncthreads();

        float msub = sce[0];
#pragma unroll
        for (int i = 1; i < 16; ++i) msub = fmaxf(msub, sce[i]);
        float newM = fmaxf(M, msub);
        float scale = __expf(M - newM);
        S *= scale;
        a.x *= scale; a.y *= scale; a.z *= scale; a.w *= scale;
        const float4* encb = (const float4*)enc + (size_t)lbase * BB * 256 + (size_t)b * 256 + tid;
#pragma unroll
        for (int i = 0; i < 16; ++i) {
            float w = __expf(sce[i] - newM);
            S += w;
            float4 v = __ldg(encb + (size_t)i * BB * 256);
            a.x += w * v.x; a.y += w * v.y; a.z += w * v.z; a.w += w * v.w;
        }
        M = newM;
        __syncthreads();
    }

    ((float4*)PCTX)[((size_t)b * 8 + chunk) * 256 + tid] = a;
    if (tid == 0) {
        MS[((size_t)b * 8 + chunk) * 2]     = M;
        MS[((size_t)b * 8 + chunk) * 2 + 1] = S;
    }
}

// combine 8 chunks: stats, attention weights, context -> fp16-packed CINP (ctx half)
__global__ void __launch_bounds__(256) k_attn_combine(
    const float* __restrict__ E, const float* __restrict__ MS,
    const float* __restrict__ PCTX,
    uint2* __restrict__ packed, float* __restrict__ attn_out)
{
    __shared__ float sm[8], ss[8];
    __shared__ float sc[HH];
    const int b = blockIdx.x, tid = threadIdx.x;
    if (tid < 8) {
        sm[tid] = MS[((size_t)b * 8 + tid) * 2];
        ss[tid] = MS[((size_t)b * 8 + tid) * 2 + 1];
    }
    __syncthreads();
    float M = sm[0];
#pragma unroll
    for (int c = 1; c < 8; ++c) M = fmaxf(M, sm[c]);
    float S = 0.f;
#pragma unroll
    for (int c = 0; c < 8; ++c) S += ss[c] * __expf(sm[c] - M);
    const float inv = 1.f / S;

    float4 a = make_float4(0.f, 0.f, 0.f, 0.f);
#pragma unroll
    for (int c = 0; c < 8; ++c) {
        float w = __expf(sm[c] - M);
        float4 v = ((const float4*)PCTX)[((size_t)b * 8 + c) * 256 + tid];
        a.x += w * v.x; a.y += w * v.y; a.z += w * v.z; a.w += w * v.w;
    }
    a.x *= inv; a.y *= inv; a.z *= inv; a.w *= inv;
    ((float4*)sc)[tid] = a;

#pragma unroll
    for (int j = 0; j < 4; ++j) {
        int l = tid + j * 256;
        attn_out[(size_t)b * LLEN + l] = __expf(E[(size_t)b * LLEN + l] - M) * inv;
    }
    __syncthreads();

    const int ts = tid >> 2, tig = tid & 3;
    const int j0 = ts * 16 + tig * 2;
    const int nf = b >> 3, lane = (b & 7) * 4 + tig;
    packed[((64 + ts) * 8 + nf) * 32 + lane] =
        make_uint2(pack_f16x2(sc[j0], sc[j0 + 1]), pack_f16x2(sc[j0 + 8], sc[j0 + 9]));
}

// ================= launcher =================
extern "C" void kernel_launch(void* const* d_in, const int* in_sizes, int n_in,
                              void* d_out, int out_size) {
    const int*   input_seq = (const int*)  d_in[0];
    const float* last_h    = (const float*)d_in[1];
    const float* enc       = (const float*)d_in[2];
    const float* emb       = (const float*)d_in[3];
    const float* W_ih      = (const float*)d_in[4];
    const float* W_hh      = (const float*)d_in[5];
    const float* b_ih      = (const float*)d_in[6];
    const float* b_hh      = (const float*)d_in[7];
    const float* W_concat  = (const float*)d_in[8];
    const float* b_concat  = (const float*)d_in[9];
    const float* W_out     = (const float*)d_in[10];
    const float* b_out     = (const float*)d_in[11];
    float* out = (float*)d_out;

    float* scratch = nullptr;
    cudaGetSymbolAddress((void**)&scratch, g_scratch);
    float* XP    = scratch;             // fp16 packed (32768 floats used)
    float* HP0   = scratch + 65536;
    float* HP1   = scratch + 131072;
    float* GX    = scratch + 196608;    // 4 slices x 196608
    float* GH    = scratch + 983040;    // 4 slices x 196608
    float* E     = scratch + 1769472;
    float* MS    = scratch + 1835008;
    float* PCTX  = scratch + 1836032;
    float* RNN   = scratch + 2360320;
    float* CINP  = scratch + 2425856;   // fp16 packed (65536 floats used)
    float* CC    = scratch + 2556928;   // 16 slices of 64x1024
    float* COUTP = scratch + 3605504;   // fp16 packed (32768 floats used)

    float* out_logits = out;
    float* out_hidden = out + (size_t)BB * VV;
    float* out_attn   = out_hidden + (size_t)2 * BB * HH;

    cudaFuncSetAttribute(k_gemm, cudaFuncAttributeMaxDynamicSharedMemorySize, GEMM_SMEM);

    k_pack3<<<dim3(64, 3), 256>>>(emb, input_seq, last_h, last_h + (size_t)BB * HH,
                                  (uint2*)XP, (uint2*)HP0, (uint2*)HP1);

    // ---- GRU layer 0 (4 K-slices x 16 ksteps = K 1024) ----
    k_gemm<<<dim3(24, 2, 4), 256, GEMM_SMEM>>>(
        W_ih, (const uint2*)XP, GX, 3072, 1024, 16, nullptr,
        W_hh, (const uint2*)HP0, GH);
    k_gates<<<dim3(64, 2), 128>>>(GX, GH, b_ih, b_hh, last_h,
                                  out_hidden, (uint2*)XP, nullptr);

    // ---- GRU layer 1 ----
    k_gemm<<<dim3(24, 2, 4), 256, GEMM_SMEM>>>(
        W_ih + (size_t)3072 * 1024, (const uint2*)XP, GX, 3072, 1024, 16, nullptr,
        W_hh + (size_t)3072 * 1024, (const uint2*)HP1, GH);
    k_gates<<<dim3(64, 2), 128>>>(GX, GH, b_ih + 3072, b_hh + 3072,
                                  last_h + (size_t)BB * HH,
                                  out_hidden + (size_t)BB * HH, (uint2*)CINP, RNN);

    // ---- fused attention ----
    k_attn_fused<<<dim3(8, 64), 256>>>(RNN, enc, E, MS, PCTX);
    k_attn_combine<<<64, 256>>>(E, MS, PCTX, (uint2*)CINP, out_attn);

    // ---- concat GEMM (16 K-slices x 8 ksteps = K 2048) ----
    k_gemm<<<dim3(8, 1, 16), 256, GEMM_SMEM>>>(
        W_concat, (const uint2*)CINP, CC, 1024, 2048, 8, nullptr,
        nullptr, nullptr, nullptr);
    k_pack_cout<<<64, 256>>>(CC, b_concat, (uint2*)COUTP);

    // ---- logits: single slice, bias folded, direct output ----
    k_gemm<<<dim3(393, 1, 1), 256, GEMM_SMEM>>>(
        W_out, (const uint2*)COUTP, out_logits, VV, 1024, 64, b_out,
        nullptr, nullptr, nullptr);

    (void)in_sizes; (void)n_in; (void)out_size;
}